// round 15
// baseline (speedup 1.0000x reference)
#include <cuda_runtime.h>
#include <cuda_fp16.h>
#include <cstdint>

#define HW_    3136
#define KTOT_  1152
#define NCHUNK 9           // 9 taps, K=128 per stage
#define NPIX_  112         // pixels per block tile = 2 image rows

// W smem-image: [e][tap][o 128][16 segs x 8 halves], seg pre-swizzled (^ (o&7))
__device__ __align__(16) __half g_Wq[8 * 9 * 128 * 128];
// packed x: [b][window (8 of 16ch)][58*58 px][16 halves, permuted {0,1,8,9,2,3,10,11,4,5,12,13,6,7,14,15}]
__device__ __align__(16) __half g_xq[(size_t)32 * 8 * 3364 * 16];

__device__ __forceinline__ uint32_t smem_u32(const void* p) {
    uint32_t a;
    asm("{ .reg .u64 t; cvta.to.shared.u64 t, %1; cvt.u32.u64 %0, t; }" : "=r"(a) : "l"(p));
    return a;
}
#define MBAR_INIT(mb, c)  asm volatile("mbarrier.init.shared.b64 [%0], %1;" :: "r"(mb), "r"(c) : "memory")
#define MBAR_EXPECT(mb, tx) \
    asm volatile("mbarrier.arrive.expect_tx.shared.b64 _, [%0], %1;" :: "r"(mb), "r"(tx) : "memory")
#define MBAR_ARRIVE(mb) \
    asm volatile("mbarrier.arrive.shared.b64 _, [%0];" :: "r"(mb) : "memory")
#define BULK_G2S(dst, src, sz, mb) \
    asm volatile("cp.async.bulk.shared::cta.global.mbarrier::complete_tx::bytes [%0], [%1], %2, [%3];" \
                 :: "r"(dst), "l"(src), "r"(sz), "r"(mb) : "memory")

#define MBAR_WAIT(mb, ph) do {                                                            \
    uint32_t _m = (mb), _p = (ph), _d;                                                    \
    asm volatile("{ .reg .pred p; mbarrier.try_wait.parity.acquire.cta.shared::cta.b64 "  \
                 "p, [%1], %2; selp.b32 %0, 1, 0, p; }"                                   \
                 : "=r"(_d) : "r"(_m), "r"(_p) : "memory");                               \
    if (!_d) {                                                                            \
        asm volatile("{ .reg .pred P1;\n\t"                                               \
            "W_%=: mbarrier.try_wait.parity.acquire.cta.shared::cta.b64 P1, [%0], %1, 0x989680;\n\t" \
            "@P1 bra.uni D_%=;\n\t bra.uni W_%=;\n\t D_%=: }"                             \
            :: "r"(_m), "r"(_p) : "memory");                                              \
    } } while (0)

__device__ __forceinline__ void ldm_x4(uint32_t* r, uint32_t addr) {
    asm volatile("ldmatrix.sync.aligned.m8n8.x4.shared.b16 {%0,%1,%2,%3}, [%4];"
                 : "=r"(r[0]), "=r"(r[1]), "=r"(r[2]), "=r"(r[3]) : "r"(addr));
}
__device__ __forceinline__ void mma16816(float* d, const uint32_t* a, uint32_t b0, uint32_t b1) {
    asm volatile("mma.sync.aligned.m16n8k16.row.col.f32.f16.f16.f32 "
                 "{%0,%1,%2,%3}, {%4,%5,%6,%7}, {%8,%9}, {%0,%1,%2,%3};"
                 : "+f"(d[0]), "+f"(d[1]), "+f"(d[2]), "+f"(d[3])
                 : "r"(a[0]), "r"(a[1]), "r"(a[2]), "r"(a[3]), "r"(b0), "r"(b1));
}

// ---------------- Fused prep: pack (blocks 0..1023) + build W_eff (1024..1167) ----------------
// build branch is register-lean: 64(cdd) x 128(o) tile, acc[8][4], warp-uniform A reads.
__global__ __launch_bounds__(256) void prep_kernel(
    const float* __restrict__ x,       // [32][128][56][56]
    const float* __restrict__ wspec,   // [8][128][1152] (cdd = c*9 + tap)
    const float* __restrict__ wch)     // [8][128][256]
{
    __shared__ float As[8][64];
    __shared__ float Bs[8][128];

    const int blk = blockIdx.x;
    if (blk < 1024) {
        // ---- pack: pad + fp16 + permuted 16-channel pack, 4-way row split ----
        const int wg = blk & 7;
        const int b  = (blk >> 3) & 31;
        const int q4 = blk >> 8;
        const float* xb = x + ((size_t)b * 128 + wg * 16) * HW_;
        uint32_t* dst = (uint32_t*)(g_xq + ((size_t)(b * 8 + wg)) * 3364 * 16);
        const int P[16] = {0, 1, 8, 9, 2, 3, 10, 11, 4, 5, 12, 13, 6, 7, 14, 15};
        const int i0 = q4 * 841;
        const int i1 = (q4 == 3) ? 3364 : (i0 + 841);
        for (int i = i0 + threadIdx.x; i < i1; i += 256) {
            int r = i / 58;
            int c = i - r * 58;
            bool in = ((unsigned)(r - 1) < 56u) && ((unsigned)(c - 1) < 56u);
            int qq = (r - 1) * 56 + (c - 1);
            uint32_t v[8];
#pragma unroll
            for (int s = 0; s < 8; s++) {
                float f0 = in ? xb[(size_t)P[2 * s] * HW_ + qq] : 0.f;
                float f1 = in ? xb[(size_t)P[2 * s + 1] * HW_ + qq] : 0.f;
                __half2 hp = __floats2half2_rn(f0, f1);
                v[s] = *(uint32_t*)&hp;
            }
            *(uint4*)(dst + (size_t)i * 8)     = make_uint4(v[0], v[1], v[2], v[3]);
            *(uint4*)(dst + (size_t)i * 8 + 4) = make_uint4(v[4], v[5], v[6], v[7]);
        }
        return;
    }

    // ---- build W_eff -> fp16 (64 cdd x 128 o tile), smem-image layout ----
    const int w  = blk - 1024;          // 0..143
    const int e  = w / 18;
    const int n0 = (w - e * 18) * 64;

    const int t  = threadIdx.x;
    const int tm = t >> 5;              // warp id 0..7 (warp-uniform)
    const int tn = t & 31;

    float acc[8][4];
#pragma unroll
    for (int i = 0; i < 8; i++)
#pragma unroll
        for (int j = 0; j < 4; j++) acc[i][j] = 0.f;

    for (int kt = 0; kt < 16; ++kt) {
#pragma unroll
        for (int i = 0; i < 2; i++) {       // As: 8x64
            int idx = t + i * 256;
            As[idx >> 6][idx & 63] = wspec[(e * 128 + kt * 8 + (idx >> 6)) * 1152 + n0 + (idx & 63)];
        }
#pragma unroll
        for (int i = 0; i < 4; i++) {       // Bs: 8x128
            int idx = t + i * 256;
            Bs[idx >> 7][idx & 127] = wch[(e * 128 + (idx & 127)) * 256 + 128 + kt * 8 + (idx >> 7)];
        }
        __syncthreads();
#pragma unroll
        for (int kk = 0; kk < 8; kk++) {
            float a[8], bv[4];
#pragma unroll
            for (int i = 0; i < 8; i++) a[i] = As[kk][tm * 8 + i];   // warp broadcast
            *(float4*)&bv[0] = *(const float4*)&Bs[kk][tn * 4];
#pragma unroll
            for (int i = 0; i < 8; i++)
#pragma unroll
                for (int j = 0; j < 4; j++) acc[i][j] += a[i] * bv[j];
        }
        __syncthreads();
    }

#pragma unroll
    for (int i = 0; i < 8; i++) {
        int cdd = n0 + tm * 8 + i;
        int cc  = cdd / 9;
        int tap = cdd - cc * 9;
        bool center = (tap == 4);
        int seg = cc >> 3;
        int w8  = cc & 7;
#pragma unroll
        for (int j = 0; j < 4; j++) {
            int o = tn * 4 + j;
            float v = acc[i][j];
            if (center) v += wch[(e * 128 + o) * 256 + cc];
            int segS = seg ^ (o & 7);
            size_t idx = (((size_t)(e * 9 + tap) * 128 + o) * 16 + segS) * 8 + w8;
            g_Wq[idx] = __float2half_rn(v);
        }
    }
}

// ---------------- Kernel B: fp16 mma.sync, K=128 per stage, 2-slot ring (UNCHANGED) ----------------
#define A_SZ      32768
#define B_SZ      29184
#define SLOT_SZ   (2 * A_SZ + B_SZ)               // 94720
#define NSTAGE    2
#define SMEM_TOTAL (1024 + NSTAGE * SLOT_SZ)      // 190464
#define A_OFF(buf, ex) (1024 + (buf) * SLOT_SZ + (ex) * A_SZ)
#define B_OFF(buf)     (1024 + (buf) * SLOT_SZ + 65536)

__global__ __launch_bounds__(512, 1) void conv_mma_kernel(
    const int* __restrict__ gate,     // [32][2]
    float*     __restrict__ out)      // [32][2][128][56][56]
{
    extern __shared__ char smem[];
    const uint32_t sb = smem_u32(smem);

    const int tid  = threadIdx.x;
    const int wid  = tid >> 5;
    const int lane = tid & 31;
    const int g    = lane >> 2;
    const int tq   = lane & 3;
    const int b    = blockIdx.y;
    const int n0   = blockIdx.x * NPIX_;
    const int h0   = blockIdx.x * 2;

    const int ex   = wid >> 3;
    const int e0   = gate[2 * b];
    const int e1   = gate[2 * b + 1];

    const __half* xqb = g_xq + (size_t)b * 8 * 3364 * 16;

    const int wg = wid & 7;
    const int mo = (wg >> 1) * 32;
    const int po = (wg & 1) * 56;
    const int colb = po ? 58 : 0;
    const int orow  = lane & 15;
    const int chalf = lane >> 4;

    float acc[2][7][4];
#pragma unroll
    for (int mt = 0; mt < 2; mt++)
#pragma unroll
        for (int j = 0; j < 7; j++)
#pragma unroll
            for (int q = 0; q < 4; q++) acc[mt][j][q] = 0.f;

    if (tid == 0) {
        MBAR_INIT(sb + 0,  1);
        MBAR_INIT(sb + 8,  1);
        MBAR_INIT(sb + 16, 16);
        MBAR_INIT(sb + 24, 16);
    }
    __syncthreads();

    auto fillStage = [&](int slot, int tap) {
        const uint32_t mb = sb + 8 * slot;
        MBAR_EXPECT(mb, (uint32_t)SLOT_SZ);
        const __half* a0 = g_Wq + ((size_t)(e0 * 9 + tap) * 128) * 128;
        const __half* a1 = g_Wq + ((size_t)(e1 * 9 + tap) * 128) * 128;
        BULK_G2S(sb + A_OFF(slot, 0), a0, A_SZ, mb);
        BULK_G2S(sb + A_OFF(slot, 1), a1, A_SZ, mb);
        const int dy = tap / 3;
        const int dx = tap - 3 * dy;
        const int poff = (h0 + dy) * 58 + dx;
#pragma unroll
        for (int fw = 0; fw < 8; fw++) {
            const __half* src = xqb + ((size_t)fw * 3364 + poff) * 16;
            BULK_G2S(sb + B_OFF(slot) + fw * 3648, src, 3648, mb);
        }
    };

    if (tid == 0) {
        fillStage(0, 0);
        fillStage(1, 1);
    }

    int fph[NSTAGE] = {0, 0};
    int eph[NSTAGE] = {0, 0};
    int buf = 0;
    for (int tap = 0; tap < NCHUNK; ++tap) {
        MBAR_WAIT(sb + 8 * buf, fph[buf]);
        fph[buf] ^= 1;

        const char* Bb = smem + B_OFF(buf);
        const uint32_t aBase = sb + A_OFF(buf, ex);

#pragma unroll
        for (int kh2 = 0; kh2 < 8; kh2++) {
            uint32_t a_h[2][4];
#pragma unroll
            for (int mt = 0; mt < 2; mt++) {
                int o = mo + mt * 16 + orow;
                int s = kh2 * 2 + chalf;
                uint32_t ah = aBase + o * 256 + ((s ^ (o & 7)) << 4);
                ldm_x4(a_h[mt], ah);
            }
#pragma unroll
            for (int j = 0; j < 7; j++) {
                const int col = colb + j * 8 + g;
                uint2 b01 = *(const uint2*)(Bb + kh2 * 3648 + col * 32 + tq * 8);
#pragma unroll
                for (int mt = 0; mt < 2; mt++)
                    mma16816(acc[mt][j], a_h[mt], b01.x, b01.y);
            }
        }

        if (lane == 0) MBAR_ARRIVE(sb + 16 + 8 * buf);

        if (tid == 0 && tap + 2 < NCHUNK) {
            MBAR_WAIT(sb + 16 + 8 * buf, eph[buf]);
            eph[buf] ^= 1;
            fillStage(buf, tap + 2);
        }

        buf ^= 1;
    }

    float* ob = out + (size_t)(2 * b + ex) * 128 * HW_;
#pragma unroll
    for (int mt = 0; mt < 2; mt++) {
#pragma unroll
        for (int j = 0; j < 7; j++) {
            int pc = n0 + po + j * 8 + tq * 2;
            int row0 = mo + mt * 16 + g;
            float2 v0 = make_float2(acc[mt][j][0], acc[mt][j][1]);
            float2 v1 = make_float2(acc[mt][j][2], acc[mt][j][3]);
            *(float2*)(ob + (size_t)row0 * HW_ + pc) = v0;
            *(float2*)(ob + (size_t)(row0 + 8) * HW_ + pc) = v1;
        }
    }
}

// ----------------------------------------------------------------------------
extern "C" void kernel_launch(void* const* d_in, const int* in_sizes, int n_in,
                              void* d_out, int out_size) {
    const float* x     = (const float*)d_in[0];   // [32,128,56,56] f32
    const int*   gate  = (const int*)  d_in[1];   // [32,2] i32
    const float* wspec = (const float*)d_in[2];   // [8,128,128,3,3] f32
    const float* wch   = (const float*)d_in[3];   // [8,128,256,1,1] f32
    float* out = (float*)d_out;                   // [32,2,128,56,56] f32

    cudaFuncSetAttribute(conv_mma_kernel,
                         cudaFuncAttributeMaxDynamicSharedMemorySize, SMEM_TOTAL);

    prep_kernel<<<1168, 256>>>(x, wspec, wch);
    conv_mma_kernel<<<dim3(28, 32), 512, SMEM_TOTAL>>>(gate, out);
}

// round 16
// speedup vs baseline: 1.1693x; 1.1693x over previous
#include <cuda_runtime.h>
#include <cuda_fp16.h>
#include <cstdint>

#define HW_    3136
#define KTOT_  1152
#define NCHUNK 9           // 9 taps, K=128 per stage
#define NPIX_  112         // pixels per block tile = 2 image rows

// W smem-image: [e][tap][o 128][16 segs x 8 halves], seg pre-swizzled (^ (o&7))
__device__ __align__(16) __half g_Wq[8 * 9 * 128 * 128];
// packed x: [b][window (8 of 16ch)][58*58 px][16 halves, permuted {0,1,8,9,2,3,10,11,4,5,12,13,6,7,14,15}]
__device__ __align__(16) __half g_xq[(size_t)32 * 8 * 3364 * 16];

__device__ __forceinline__ uint32_t smem_u32(const void* p) {
    uint32_t a;
    asm("{ .reg .u64 t; cvta.to.shared.u64 t, %1; cvt.u32.u64 %0, t; }" : "=r"(a) : "l"(p));
    return a;
}
#define MBAR_INIT(mb, c)  asm volatile("mbarrier.init.shared.b64 [%0], %1;" :: "r"(mb), "r"(c) : "memory")
#define MBAR_EXPECT(mb, tx) \
    asm volatile("mbarrier.arrive.expect_tx.shared.b64 _, [%0], %1;" :: "r"(mb), "r"(tx) : "memory")
#define MBAR_ARRIVE(mb) \
    asm volatile("mbarrier.arrive.shared.b64 _, [%0];" :: "r"(mb) : "memory")
#define BULK_G2S(dst, src, sz, mb) \
    asm volatile("cp.async.bulk.shared::cta.global.mbarrier::complete_tx::bytes [%0], [%1], %2, [%3];" \
                 :: "r"(dst), "l"(src), "r"(sz), "r"(mb) : "memory")

#define MBAR_WAIT(mb, ph) do {                                                            \
    uint32_t _m = (mb), _p = (ph), _d;                                                    \
    asm volatile("{ .reg .pred p; mbarrier.try_wait.parity.acquire.cta.shared::cta.b64 "  \
                 "p, [%1], %2; selp.b32 %0, 1, 0, p; }"                                   \
                 : "=r"(_d) : "r"(_m), "r"(_p) : "memory");                               \
    if (!_d) {                                                                            \
        asm volatile("{ .reg .pred P1;\n\t"                                               \
            "W_%=: mbarrier.try_wait.parity.acquire.cta.shared::cta.b64 P1, [%0], %1, 0x989680;\n\t" \
            "@P1 bra.uni D_%=;\n\t bra.uni W_%=;\n\t D_%=: }"                             \
            :: "r"(_m), "r"(_p) : "memory");                                              \
    } } while (0)

// relaxed variant: only for producer waits whose post-wait accesses are async-proxy
#define MBAR_WAIT_RELAXED(mb, ph) do {                                                    \
    uint32_t _m = (mb), _p = (ph), _d;                                                    \
    asm volatile("{ .reg .pred p; mbarrier.try_wait.parity.relaxed.cta.shared::cta.b64 "  \
                 "p, [%1], %2; selp.b32 %0, 1, 0, p; }"                                   \
                 : "=r"(_d) : "r"(_m), "r"(_p) : "memory");                               \
    if (!_d) {                                                                            \
        asm volatile("{ .reg .pred P1;\n\t"                                               \
            "W_%=: mbarrier.try_wait.parity.relaxed.cta.shared::cta.b64 P1, [%0], %1, 0x989680;\n\t" \
            "@P1 bra.uni D_%=;\n\t bra.uni W_%=;\n\t D_%=: }"                             \
            :: "r"(_m), "r"(_p) : "memory");                                              \
    } } while (0)

__device__ __forceinline__ void ldm_x4(uint32_t* r, uint32_t addr) {
    asm volatile("ldmatrix.sync.aligned.m8n8.x4.shared.b16 {%0,%1,%2,%3}, [%4];"
                 : "=r"(r[0]), "=r"(r[1]), "=r"(r[2]), "=r"(r[3]) : "r"(addr));
}
__device__ __forceinline__ void mma16816(float* d, const uint32_t* a, uint32_t b0, uint32_t b1) {
    asm volatile("mma.sync.aligned.m16n8k16.row.col.f32.f16.f16.f32 "
                 "{%0,%1,%2,%3}, {%4,%5,%6,%7}, {%8,%9}, {%0,%1,%2,%3};"
                 : "+f"(d[0]), "+f"(d[1]), "+f"(d[2]), "+f"(d[3])
                 : "r"(a[0]), "r"(a[1]), "r"(a[2]), "r"(a[3]), "r"(b0), "r"(b1));
}

// ---------------- Prep 1: pack — pad + fp16 + permuted 16-channel pack (4-way split) ----------------
__global__ __launch_bounds__(256) void pack_kernel(const float* __restrict__ x) {
    const int blk = blockIdx.x;          // 0..1023
    const int wg = blk & 7;
    const int b  = (blk >> 3) & 31;
    const int q4 = blk >> 8;
    const float* xb = x + ((size_t)b * 128 + wg * 16) * HW_;
    uint32_t* dst = (uint32_t*)(g_xq + ((size_t)(b * 8 + wg)) * 3364 * 16);
    const int P[16] = {0, 1, 8, 9, 2, 3, 10, 11, 4, 5, 12, 13, 6, 7, 14, 15};
    const int i0 = q4 * 841;
    const int i1 = (q4 == 3) ? 3364 : (i0 + 841);
    for (int i = i0 + threadIdx.x; i < i1; i += 256) {
        int r = i / 58;
        int c = i - r * 58;
        bool in = ((unsigned)(r - 1) < 56u) && ((unsigned)(c - 1) < 56u);
        int qq = (r - 1) * 56 + (c - 1);
        uint32_t v[8];
#pragma unroll
        for (int s = 0; s < 8; s++) {
            float f0 = in ? xb[(size_t)P[2 * s] * HW_ + qq] : 0.f;
            float f1 = in ? xb[(size_t)P[2 * s + 1] * HW_ + qq] : 0.f;
            __half2 hp = __floats2half2_rn(f0, f1);
            v[s] = *(uint32_t*)&hp;
        }
        *(uint4*)(dst + (size_t)i * 8)     = make_uint4(v[0], v[1], v[2], v[3]);
        *(uint4*)(dst + (size_t)i * 8 + 4) = make_uint4(v[4], v[5], v[6], v[7]);
    }
}

// ---------------- Prep 2: build W_eff (lean: 64 cdd x 128 o per block, 144 blocks) ----------------
__global__ __launch_bounds__(256) void build_weff_kernel(
    const float* __restrict__ wspec,   // [8][128][1152] (cdd = c*9 + tap)
    const float* __restrict__ wch)     // [8][128][256]
{
    __shared__ float As[8][64];
    __shared__ float Bs[8][128];

    const int w  = blockIdx.x;          // 0..143
    const int e  = w / 18;
    const int n0 = (w - e * 18) * 64;

    const int t  = threadIdx.x;
    const int tm = t >> 5;              // warp id 0..7 (warp-uniform)
    const int tn = t & 31;

    float acc[8][4];
#pragma unroll
    for (int i = 0; i < 8; i++)
#pragma unroll
        for (int j = 0; j < 4; j++) acc[i][j] = 0.f;

    for (int kt = 0; kt < 16; ++kt) {
#pragma unroll
        for (int i = 0; i < 2; i++) {       // As: 8x64
            int idx = t + i * 256;
            As[idx >> 6][idx & 63] = wspec[(e * 128 + kt * 8 + (idx >> 6)) * 1152 + n0 + (idx & 63)];
        }
#pragma unroll
        for (int i = 0; i < 4; i++) {       // Bs: 8x128
            int idx = t + i * 256;
            Bs[idx >> 7][idx & 127] = wch[(e * 128 + (idx & 127)) * 256 + 128 + kt * 8 + (idx >> 7)];
        }
        __syncthreads();
#pragma unroll
        for (int kk = 0; kk < 8; kk++) {
            float a[8], bv[4];
#pragma unroll
            for (int i = 0; i < 8; i++) a[i] = As[kk][tm * 8 + i];   // warp broadcast
            *(float4*)&bv[0] = *(const float4*)&Bs[kk][tn * 4];
#pragma unroll
            for (int i = 0; i < 8; i++)
#pragma unroll
                for (int j = 0; j < 4; j++) acc[i][j] += a[i] * bv[j];
        }
        __syncthreads();
    }

#pragma unroll
    for (int i = 0; i < 8; i++) {
        int cdd = n0 + tm * 8 + i;
        int cc  = cdd / 9;
        int tap = cdd - cc * 9;
        bool center = (tap == 4);
        int seg = cc >> 3;
        int w8  = cc & 7;
#pragma unroll
        for (int j = 0; j < 4; j++) {
            int o = tn * 4 + j;
            float v = acc[i][j];
            if (center) v += wch[(e * 128 + o) * 256 + cc];
            int segS = seg ^ (o & 7);
            size_t idx = (((size_t)(e * 9 + tap) * 128 + o) * 16 + segS) * 8 + w8;
            g_Wq[idx] = __float2half_rn(v);
        }
    }
}

// ---------------- Kernel B: fp16 mma.sync, K=128 per stage, 2-slot ring ----------------
#define A_SZ      32768
#define B_SZ      29184
#define SLOT_SZ   (2 * A_SZ + B_SZ)               // 94720
#define NSTAGE    2
#define SMEM_TOTAL (1024 + NSTAGE * SLOT_SZ)      // 190464
#define A_OFF(buf, ex) (1024 + (buf) * SLOT_SZ + (ex) * A_SZ)
#define B_OFF(buf)     (1024 + (buf) * SLOT_SZ + 65536)
// mbarriers: full[slot] at sb+8*slot, empty[slot] at sb+16+8*slot

__global__ __launch_bounds__(512, 1) void conv_mma_kernel(
    const int* __restrict__ gate,     // [32][2]
    float*     __restrict__ out)      // [32][2][128][56][56]
{
    extern __shared__ char smem[];
    const uint32_t sb = smem_u32(smem);

    const int tid  = threadIdx.x;
    const int wid  = tid >> 5;
    const int lane = tid & 31;
    const int g    = lane >> 2;
    const int tq   = lane & 3;
    const int b    = blockIdx.y;
    const int n0   = blockIdx.x * NPIX_;
    const int h0   = blockIdx.x * 2;

    const int ex   = wid >> 3;            // this warp's gate column
    const int e0   = gate[2 * b];
    const int e1   = gate[2 * b + 1];

    const __half* xqb = g_xq + (size_t)b * 8 * 3364 * 16;

    // warp tile within its expert half: 32(o) x 56(p)
    const int wg = wid & 7;
    const int mo = (wg >> 1) * 32;
    const int po = (wg & 1) * 56;
    const int colb = po ? 58 : 0;         // +2 seam offset for second image row
    const int orow  = lane & 15;
    const int chalf = lane >> 4;

    float acc[2][7][4];
#pragma unroll
    for (int mt = 0; mt < 2; mt++)
#pragma unroll
        for (int j = 0; j < 7; j++)
#pragma unroll
            for (int q = 0; q < 4; q++) acc[mt][j][q] = 0.f;

    if (tid == 0) {
        MBAR_INIT(sb + 0,  1);    // full slot 0 (tx-based)
        MBAR_INIT(sb + 8,  1);    // full slot 1
        MBAR_INIT(sb + 16, 16);   // empty slot 0 (one arrive per warp)
        MBAR_INIT(sb + 24, 16);   // empty slot 1
    }
    __syncthreads();

    // producer: tid 0 issues 10 bulk copies per stage (2 A + 8 B)
    auto fillStage = [&](int slot, int tap) {
        const uint32_t mb = sb + 8 * slot;
        MBAR_EXPECT(mb, (uint32_t)SLOT_SZ);
        const __half* a0 = g_Wq + ((size_t)(e0 * 9 + tap) * 128) * 128;
        const __half* a1 = g_Wq + ((size_t)(e1 * 9 + tap) * 128) * 128;
        BULK_G2S(sb + A_OFF(slot, 0), a0, A_SZ, mb);
        BULK_G2S(sb + A_OFF(slot, 1), a1, A_SZ, mb);
        const int dy = tap / 3;
        const int dx = tap - 3 * dy;
        const int poff = (h0 + dy) * 58 + dx;    // first row; 114 px span covers both rows
#pragma unroll
        for (int fw = 0; fw < 8; fw++) {
            const __half* src = xqb + ((size_t)fw * 3364 + poff) * 16;
            BULK_G2S(sb + B_OFF(slot) + fw * 3648, src, 3648, mb);
        }
    };

    if (tid == 0) {
        fillStage(0, 0);
        fillStage(1, 1);
    }

    int fph[NSTAGE] = {0, 0};
    int eph[NSTAGE] = {0, 0};
    int buf = 0;
    for (int tap = 0; tap < NCHUNK; ++tap) {
        MBAR_WAIT(sb + 8 * buf, fph[buf]);
        fph[buf] ^= 1;

        const char* Bb = smem + B_OFF(buf);
        const uint32_t aBase = sb + A_OFF(buf, ex);

#pragma unroll
        for (int kh2 = 0; kh2 < 8; kh2++) {
            uint32_t a_h[2][4];
#pragma unroll
            for (int mt = 0; mt < 2; mt++) {
                int o = mo + mt * 16 + orow;
                int s = kh2 * 2 + chalf;
                uint32_t ah = aBase + o * 256 + ((s ^ (o & 7)) << 4);
                ldm_x4(a_h[mt], ah);
            }
#pragma unroll
            for (int j = 0; j < 7; j++) {
                const int col = colb + j * 8 + g;
                uint2 b01 = *(const uint2*)(Bb + kh2 * 3648 + col * 32 + tq * 8);
#pragma unroll
                for (int mt = 0; mt < 2; mt++)
                    mma16816(acc[mt][j], a_h[mt], b01.x, b01.y);
            }
        }

        // per-warp slot release (release semantics orders the LDS reads above)
        if (lane == 0) MBAR_ARRIVE(sb + 16 + 8 * buf);

        // producer: wait until all 16 warps released the slot, then refill it.
        // relaxed is safe: post-wait accesses are async-proxy bulk copies only.
        if (tid == 0 && tap + 2 < NCHUNK) {
            MBAR_WAIT_RELAXED(sb + 16 + 8 * buf, eph[buf]);
            eph[buf] ^= 1;
            fillStage(buf, tap + 2);
        }

        buf ^= 1;
    }

    // ---- epilogue ----
    float* ob = out + (size_t)(2 * b + ex) * 128 * HW_;
#pragma unroll
    for (int mt = 0; mt < 2; mt++) {
#pragma unroll
        for (int j = 0; j < 7; j++) {
            int pc = n0 + po + j * 8 + tq * 2;
            int row0 = mo + mt * 16 + g;
            float2 v0 = make_float2(acc[mt][j][0], acc[mt][j][1]);
            float2 v1 = make_float2(acc[mt][j][2], acc[mt][j][3]);
            *(float2*)(ob + (size_t)row0 * HW_ + pc) = v0;
            *(float2*)(ob + (size_t)(row0 + 8) * HW_ + pc) = v1;
        }
    }
}

// ----------------------------------------------------------------------------
extern "C" void kernel_launch(void* const* d_in, const int* in_sizes, int n_in,
                              void* d_out, int out_size) {
    const float* x     = (const float*)d_in[0];   // [32,128,56,56] f32
    const int*   gate  = (const int*)  d_in[1];   // [32,2] i32
    const float* wspec = (const float*)d_in[2];   // [8,128,128,3,3] f32
    const float* wch   = (const float*)d_in[3];   // [8,128,256,1,1] f32
    float* out = (float*)d_out;                   // [32,2,128,56,56] f32

    cudaFuncSetAttribute(conv_mma_kernel,
                         cudaFuncAttributeMaxDynamicSharedMemorySize, SMEM_TOTAL);

    build_weff_kernel<<<144, 256>>>(wspec, wch);
    pack_kernel<<<1024, 256>>>(x);
    conv_mma_kernel<<<dim3(28, 32), 512, SMEM_TOTAL>>>(gate, out);
}

// round 17
// speedup vs baseline: 1.1938x; 1.0209x over previous
#include <cuda_runtime.h>
#include <cuda_fp16.h>
#include <cstdint>

#define HW_    3136
#define KTOT_  1152
#define NCHUNK 9           // 9 taps, K=128 per stage
#define NPIX_  112         // pixels per block tile = 2 image rows

// W smem-image: [e][tap][o 128][16 segs x 8 halves], seg pre-swizzled (^ (o&7))
__device__ __align__(16) __half g_Wq[8 * 9 * 128 * 128];
// packed x: [b][window (8 of 16ch)][58*58 px][16 halves, permuted {0,1,8,9,2,3,10,11,4,5,12,13,6,7,14,15}]
__device__ __align__(16) __half g_xq[(size_t)32 * 8 * 3364 * 16];

__device__ __forceinline__ uint32_t smem_u32(const void* p) {
    uint32_t a;
    asm("{ .reg .u64 t; cvta.to.shared.u64 t, %1; cvt.u32.u64 %0, t; }" : "=r"(a) : "l"(p));
    return a;
}
#define MBAR_INIT(mb, c)  asm volatile("mbarrier.init.shared.b64 [%0], %1;" :: "r"(mb), "r"(c) : "memory")
#define MBAR_EXPECT(mb, tx) \
    asm volatile("mbarrier.arrive.expect_tx.shared.b64 _, [%0], %1;" :: "r"(mb), "r"(tx) : "memory")
#define MBAR_ARRIVE(mb) \
    asm volatile("mbarrier.arrive.shared.b64 _, [%0];" :: "r"(mb) : "memory")
#define BULK_G2S(dst, src, sz, mb) \
    asm volatile("cp.async.bulk.shared::cta.global.mbarrier::complete_tx::bytes [%0], [%1], %2, [%3];" \
                 :: "r"(dst), "l"(src), "r"(sz), "r"(mb) : "memory")

#define MBAR_WAIT(mb, ph) do {                                                            \
    uint32_t _m = (mb), _p = (ph), _d;                                                    \
    asm volatile("{ .reg .pred p; mbarrier.try_wait.parity.acquire.cta.shared::cta.b64 "  \
                 "p, [%1], %2; selp.b32 %0, 1, 0, p; }"                                   \
                 : "=r"(_d) : "r"(_m), "r"(_p) : "memory");                               \
    if (!_d) {                                                                            \
        asm volatile("{ .reg .pred P1;\n\t"                                               \
            "W_%=: mbarrier.try_wait.parity.acquire.cta.shared::cta.b64 P1, [%0], %1, 0x989680;\n\t" \
            "@P1 bra.uni D_%=;\n\t bra.uni W_%=;\n\t D_%=: }"                             \
            :: "r"(_m), "r"(_p) : "memory");                                              \
    } } while (0)

// relaxed variant: only for producer waits whose post-wait accesses are async-proxy
#define MBAR_WAIT_RELAXED(mb, ph) do {                                                    \
    uint32_t _m = (mb), _p = (ph), _d;                                                    \
    asm volatile("{ .reg .pred p; mbarrier.try_wait.parity.relaxed.cta.shared::cta.b64 "  \
                 "p, [%1], %2; selp.b32 %0, 1, 0, p; }"                                   \
                 : "=r"(_d) : "r"(_m), "r"(_p) : "memory");                               \
    if (!_d) {                                                                            \
        asm volatile("{ .reg .pred P1;\n\t"                                               \
            "W_%=: mbarrier.try_wait.parity.relaxed.cta.shared::cta.b64 P1, [%0], %1, 0x989680;\n\t" \
            "@P1 bra.uni D_%=;\n\t bra.uni W_%=;\n\t D_%=: }"                             \
            :: "r"(_m), "r"(_p) : "memory");                                              \
    } } while (0)

__device__ __forceinline__ void ldm_x4(uint32_t* r, uint32_t addr) {
    asm volatile("ldmatrix.sync.aligned.m8n8.x4.shared.b16 {%0,%1,%2,%3}, [%4];"
                 : "=r"(r[0]), "=r"(r[1]), "=r"(r[2]), "=r"(r[3]) : "r"(addr));
}
__device__ __forceinline__ void mma16816(float* d, const uint32_t* a, uint32_t b0, uint32_t b1) {
    asm volatile("mma.sync.aligned.m16n8k16.row.col.f32.f16.f16.f32 "
                 "{%0,%1,%2,%3}, {%4,%5,%6,%7}, {%8,%9}, {%0,%1,%2,%3};"
                 : "+f"(d[0]), "+f"(d[1]), "+f"(d[2]), "+f"(d[3])
                 : "r"(a[0]), "r"(a[1]), "r"(a[2]), "r"(a[3]), "r"(b0), "r"(b1));
}

// ---------------- Prep 1: pack — pad + fp16 + permuted 16-channel pack (4-way split) ----------------
__global__ __launch_bounds__(256) void pack_kernel(const float* __restrict__ x) {
    const int blk = blockIdx.x;          // 0..1023
    const int wg = blk & 7;
    const int b  = (blk >> 3) & 31;
    const int q4 = blk >> 8;
    const float* xb = x + ((size_t)b * 128 + wg * 16) * HW_;
    uint32_t* dst = (uint32_t*)(g_xq + ((size_t)(b * 8 + wg)) * 3364 * 16);
    const int P[16] = {0, 1, 8, 9, 2, 3, 10, 11, 4, 5, 12, 13, 6, 7, 14, 15};
    const int i0 = q4 * 841;
    const int i1 = (q4 == 3) ? 3364 : (i0 + 841);
    for (int i = i0 + threadIdx.x; i < i1; i += 256) {
        int r = i / 58;
        int c = i - r * 58;
        bool in = ((unsigned)(r - 1) < 56u) && ((unsigned)(c - 1) < 56u);
        int qq = (r - 1) * 56 + (c - 1);
        uint32_t v[8];
#pragma unroll
        for (int s = 0; s < 8; s++) {
            float f0 = in ? xb[(size_t)P[2 * s] * HW_ + qq] : 0.f;
            float f1 = in ? xb[(size_t)P[2 * s + 1] * HW_ + qq] : 0.f;
            __half2 hp = __floats2half2_rn(f0, f1);
            v[s] = *(uint32_t*)&hp;
        }
        *(uint4*)(dst + (size_t)i * 8)     = make_uint4(v[0], v[1], v[2], v[3]);
        *(uint4*)(dst + (size_t)i * 8 + 4) = make_uint4(v[4], v[5], v[6], v[7]);
    }
}

// ---------------- Prep 2: build W_eff — latency-optimized ----------------
// 576 blocks: e = blk/72, cdd tile = 16. Register prefetch double-buffer over K.
__global__ __launch_bounds__(256) void build_weff_kernel(
    const float* __restrict__ wspec,   // [8][128][1152] (cdd = c*9 + tap)
    const float* __restrict__ wch)     // [8][128][256]
{
    __shared__ float As[8][16];
    __shared__ float Bs[8][132];       // padded: store pattern hits all 32 banks

    const int blk = blockIdx.x;        // 0..575
    const int e   = blk / 72;
    const int n0  = (blk - e * 72) * 16;

    const int t  = threadIdx.x;
    const int tm = t >> 5;             // warp 0..7 -> cdd rows tm*2, tm*2+1
    const int tn = t & 31;             // o = tn*4 + j

    const bool aact = (t < 128);
    const int kla = t >> 4;            // 0..7
    const int ca  = t & 15;
    const int blo = t & 7;             // Bs kl
    const int bo0 = t >> 3;            // Bs o base (0..31); +32*i per chunk

    float acc[2][4];
#pragma unroll
    for (int i = 0; i < 2; i++)
#pragma unroll
        for (int j = 0; j < 4; j++) acc[i][j] = 0.f;

    // prefetch kt = 0
    float a_r = 0.f;
    if (aact) a_r = wspec[(e * 128 + kla) * 1152 + n0 + ca];
    float b_r[4];
#pragma unroll
    for (int i = 0; i < 4; i++)
        b_r[i] = wch[(e * 128 + bo0 + 32 * i) * 256 + 128 + blo];

    for (int kt = 0; kt < 16; ++kt) {
        if (aact) As[kla][ca] = a_r;
#pragma unroll
        for (int i = 0; i < 4; i++)
            Bs[blo][bo0 + 32 * i] = b_r[i];
        __syncthreads();

        if (kt + 1 < 16) {             // issue next-stage loads before compute
            if (aact) a_r = wspec[(e * 128 + (kt + 1) * 8 + kla) * 1152 + n0 + ca];
#pragma unroll
            for (int i = 0; i < 4; i++)
                b_r[i] = wch[(e * 128 + bo0 + 32 * i) * 256 + 128 + (kt + 1) * 8 + blo];
        }

#pragma unroll
        for (int kk = 0; kk < 8; kk++) {
            float a0 = As[kk][tm * 2];         // warp broadcast
            float a1 = As[kk][tm * 2 + 1];
            float bv[4];
            *(float4*)bv = *(const float4*)&Bs[kk][tn * 4];
#pragma unroll
            for (int j = 0; j < 4; j++) {
                acc[0][j] += a0 * bv[j];
                acc[1][j] += a1 * bv[j];
            }
        }
        __syncthreads();
    }

#pragma unroll
    for (int i = 0; i < 2; i++) {
        int cdd = n0 + tm * 2 + i;
        int cc  = cdd / 9;
        int tap = cdd - cc * 9;
        bool center = (tap == 4);
        int seg = cc >> 3;
        int w8  = cc & 7;
#pragma unroll
        for (int j = 0; j < 4; j++) {
            int o = tn * 4 + j;
            float v = acc[i][j];
            if (center) v += wch[(e * 128 + o) * 256 + cc];
            int segS = seg ^ (o & 7);
            size_t idx = (((size_t)(e * 9 + tap) * 128 + o) * 16 + segS) * 8 + w8;
            g_Wq[idx] = __float2half_rn(v);
        }
    }
}

// ---------------- Kernel B: fp16 mma.sync, K=128 per stage, 2-slot ring (UNCHANGED) ----------------
#define A_SZ      32768
#define B_SZ      29184
#define SLOT_SZ   (2 * A_SZ + B_SZ)               // 94720
#define NSTAGE    2
#define SMEM_TOTAL (1024 + NSTAGE * SLOT_SZ)      // 190464
#define A_OFF(buf, ex) (1024 + (buf) * SLOT_SZ + (ex) * A_SZ)
#define B_OFF(buf)     (1024 + (buf) * SLOT_SZ + 65536)
// mbarriers: full[slot] at sb+8*slot, empty[slot] at sb+16+8*slot

__global__ __launch_bounds__(512, 1) void conv_mma_kernel(
    const int* __restrict__ gate,     // [32][2]
    float*     __restrict__ out)      // [32][2][128][56][56]
{
    extern __shared__ char smem[];
    const uint32_t sb = smem_u32(smem);

    const int tid  = threadIdx.x;
    const int wid  = tid >> 5;
    const int lane = tid & 31;
    const int g    = lane >> 2;
    const int tq   = lane & 3;
    const int b    = blockIdx.y;
    const int n0   = blockIdx.x * NPIX_;
    const int h0   = blockIdx.x * 2;

    const int ex   = wid >> 3;            // this warp's gate column
    const int e0   = gate[2 * b];
    const int e1   = gate[2 * b + 1];

    const __half* xqb = g_xq + (size_t)b * 8 * 3364 * 16;

    // warp tile within its expert half: 32(o) x 56(p)
    const int wg = wid & 7;
    const int mo = (wg >> 1) * 32;
    const int po = (wg & 1) * 56;
    const int colb = po ? 58 : 0;         // +2 seam offset for second image row
    const int orow  = lane & 15;
    const int chalf = lane >> 4;

    float acc[2][7][4];
#pragma unroll
    for (int mt = 0; mt < 2; mt++)
#pragma unroll
        for (int j = 0; j < 7; j++)
#pragma unroll
            for (int q = 0; q < 4; q++) acc[mt][j][q] = 0.f;

    if (tid == 0) {
        MBAR_INIT(sb + 0,  1);    // full slot 0 (tx-based)
        MBAR_INIT(sb + 8,  1);    // full slot 1
        MBAR_INIT(sb + 16, 16);   // empty slot 0 (one arrive per warp)
        MBAR_INIT(sb + 24, 16);   // empty slot 1
    }
    __syncthreads();

    // producer: tid 0 issues 10 bulk copies per stage (2 A + 8 B)
    auto fillStage = [&](int slot, int tap) {
        const uint32_t mb = sb + 8 * slot;
        MBAR_EXPECT(mb, (uint32_t)SLOT_SZ);
        const __half* a0 = g_Wq + ((size_t)(e0 * 9 + tap) * 128) * 128;
        const __half* a1 = g_Wq + ((size_t)(e1 * 9 + tap) * 128) * 128;
        BULK_G2S(sb + A_OFF(slot, 0), a0, A_SZ, mb);
        BULK_G2S(sb + A_OFF(slot, 1), a1, A_SZ, mb);
        const int dy = tap / 3;
        const int dx = tap - 3 * dy;
        const int poff = (h0 + dy) * 58 + dx;    // first row; 114 px span covers both rows
#pragma unroll
        for (int fw = 0; fw < 8; fw++) {
            const __half* src = xqb + ((size_t)fw * 3364 + poff) * 16;
            BULK_G2S(sb + B_OFF(slot) + fw * 3648, src, 3648, mb);
        }
    };

    if (tid == 0) {
        fillStage(0, 0);
        fillStage(1, 1);
    }

    int fph[NSTAGE] = {0, 0};
    int eph[NSTAGE] = {0, 0};
    int buf = 0;
    for (int tap = 0; tap < NCHUNK; ++tap) {
        MBAR_WAIT(sb + 8 * buf, fph[buf]);
        fph[buf] ^= 1;

        const char* Bb = smem + B_OFF(buf);
        const uint32_t aBase = sb + A_OFF(buf, ex);

#pragma unroll
        for (int kh2 = 0; kh2 < 8; kh2++) {
            uint32_t a_h[2][4];
#pragma unroll
            for (int mt = 0; mt < 2; mt++) {
                int o = mo + mt * 16 + orow;
                int s = kh2 * 2 + chalf;
                uint32_t ah = aBase + o * 256 + ((s ^ (o & 7)) << 4);
                ldm_x4(a_h[mt], ah);
            }
#pragma unroll
            for (int j = 0; j < 7; j++) {
                const int col = colb + j * 8 + g;
                uint2 b01 = *(const uint2*)(Bb + kh2 * 3648 + col * 32 + tq * 8);
#pragma unroll
                for (int mt = 0; mt < 2; mt++)
                    mma16816(acc[mt][j], a_h[mt], b01.x, b01.y);
            }
        }

        // per-warp slot release (release semantics orders the LDS reads above)
        if (lane == 0) MBAR_ARRIVE(sb + 16 + 8 * buf);

        // producer: wait until all 16 warps released the slot, then refill it.
        // relaxed is safe: post-wait accesses are async-proxy bulk copies only.
        if (tid == 0 && tap + 2 < NCHUNK) {
            MBAR_WAIT_RELAXED(sb + 16 + 8 * buf, eph[buf]);
            eph[buf] ^= 1;
            fillStage(buf, tap + 2);
        }

        buf ^= 1;
    }

    // ---- epilogue ----
    float* ob = out + (size_t)(2 * b + ex) * 128 * HW_;
#pragma unroll
    for (int mt = 0; mt < 2; mt++) {
#pragma unroll
        for (int j = 0; j < 7; j++) {
            int pc = n0 + po + j * 8 + tq * 2;
            int row0 = mo + mt * 16 + g;
            float2 v0 = make_float2(acc[mt][j][0], acc[mt][j][1]);
            float2 v1 = make_float2(acc[mt][j][2], acc[mt][j][3]);
            *(float2*)(ob + (size_t)row0 * HW_ + pc) = v0;
            *(float2*)(ob + (size_t)(row0 + 8) * HW_ + pc) = v1;
        }
    }
}

// ----------------------------------------------------------------------------
extern "C" void kernel_launch(void* const* d_in, const int* in_sizes, int n_in,
                              void* d_out, int out_size) {
    const float* x     = (const float*)d_in[0];   // [32,128,56,56] f32
    const int*   gate  = (const int*)  d_in[1];   // [32,2] i32
    const float* wspec = (const float*)d_in[2];   // [8,128,128,3,3] f32
    const float* wch   = (const float*)d_in[3];   // [8,128,256,1,1] f32
    float* out = (float*)d_out;                   // [32,2,128,56,56] f32

    cudaFuncSetAttribute(conv_mma_kernel,
                         cudaFuncAttributeMaxDynamicSharedMemorySize, SMEM_TOTAL);

    build_weff_kernel<<<576, 256>>>(wspec, wch);
    pack_kernel<<<1024, 256>>>(x);
    conv_mma_kernel<<<dim3(28, 32), 512, SMEM_TOTAL>>>(gate, out);
}